// round 9
// baseline (speedup 1.0000x reference)
#include <cuda_runtime.h>
#include <math.h>

#define EPS 1e-8f
#define TARGET_RADIUS 0.99f
#define Bsz 32
#define Dsz 1024
#define BD (Bsz * Dsz)
#define NBLK 128   // recurrence grid size (single wave)
#define RTHREADS 512

typedef unsigned long long ull;

// ---------------- packed f32x2 helpers (sm_103a) ----------------
__device__ __forceinline__ ull f32x2_pack(float lo, float hi) {
    ull r;
    asm("mov.b64 %0, {%1, %2};" : "=l"(r) : "f"(lo), "f"(hi));
    return r;
}
__device__ __forceinline__ void f32x2_unpack(ull p, float& lo, float& hi) {
    asm("mov.b64 {%0, %1}, %2;" : "=f"(lo), "=f"(hi) : "l"(p));
}
__device__ __forceinline__ ull f32x2_fma(ull a, ull b, ull c) {
    ull d;
    asm("fma.rn.f32x2 %0, %1, %2, %3;" : "=l"(d) : "l"(a), "l"(b), "l"(c));
    return d;
}

// ---------------- device scratch ----------------
__device__ float g_Wx[2048L * Bsz * Dsz];       // precomputed x @ W_x^T  (268 MB)
__device__ float g_scale;                       // spectral scaling of W_h
__device__ unsigned int g_flag[2 * 128 * 32];   // per-CTA per-chain step flags, 128B padded

// ---------------- scoped atomic helpers ----------------
__device__ __forceinline__ unsigned int ld_acquire_gpu(const unsigned int* p) {
    unsigned int v;
    asm volatile("ld.acquire.gpu.global.u32 %0, [%1];" : "=r"(v) : "l"(p) : "memory");
    return v;
}
__device__ __forceinline__ void red_release_gpu_add(unsigned int* p, unsigned int v) {
    asm volatile("red.release.gpu.global.add.u32 [%0], %1;" :: "l"(p), "r"(v) : "memory");
}

// ---------------- reset + h0 copy ----------------
__global__ void reset_copy_kernel(const float* __restrict__ h0, float* __restrict__ hglob) {
    int i = blockIdx.x * blockDim.x + threadIdx.x;
    if (i < 2 * 128 * 32) g_flag[i] = 0u;
    if (i < BD) hglob[i] = h0[i];
}

// ---------------- block reduction helper ----------------
__device__ __forceinline__ float block_reduce_sum(float v, float* red) {
    int lane = threadIdx.x & 31, w = threadIdx.x >> 5;
    #pragma unroll
    for (int o = 16; o; o >>= 1) v += __shfl_xor_sync(0xffffffffu, v, o);
    if (lane == 0) red[w] = v;
    __syncthreads();
    if (w == 0) {
        float r = (lane < (int)(blockDim.x >> 5)) ? red[lane] : 0.0f;
        #pragma unroll
        for (int o = 16; o; o >>= 1) r += __shfl_xor_sync(0xffffffffu, r, o);
        if (lane == 0) red[0] = r;
    }
    __syncthreads();
    float out = red[0];
    __syncthreads();
    return out;
}

// ---------------- spectral norm (1 CTA, 1024 threads) ----------------
__global__ __launch_bounds__(1024) void spectral_kernel(
    const float* __restrict__ W, const float* __restrict__ u0) {
    __shared__ float u_sh[Dsz];
    __shared__ float v_sh[Dsz];
    __shared__ float red[32];
    int i = threadIdx.x;

    float u0v = u0[i];
    float n0 = sqrtf(block_reduce_sum(u0v * u0v, red));
    u_sh[i] = u0v / n0;     // reference: no eps on the initial normalize
    __syncthreads();

    float sigma = 0.0f;
    for (int it = 0; it < 3; it++) {
        float acc = 0.0f;
        #pragma unroll 8
        for (int k = 0; k < Dsz; k++) acc += W[k * Dsz + i] * u_sh[k];
        float nv = sqrtf(block_reduce_sum(acc * acc, red));
        v_sh[i] = acc / (nv + EPS);
        __syncthreads();
        float acc2 = 0.0f;
        #pragma unroll 8
        for (int c = 0; c < Dsz; c++) acc2 += W[i * Dsz + c] * v_sh[c];
        float ss = block_reduce_sum(acc2 * acc2, red);
        float nu = sqrtf(ss);
        u_sh[i] = acc2 / (nu + EPS);
        __syncthreads();
        sigma = ss / (nu + EPS);
    }
    if (i == 0) g_scale = TARGET_RADIUS / (sigma + EPS);
}

// ---------------- Wx GEMM:  C[M][1024] = A[M][1024] * B[1024][1024]^T ----------------
// FFMA2 + software prefetch: next k-tile's LDG issues before the compute
// phase, hiding global latency behind ~2000 cycles of FMA work.
__global__ __launch_bounds__(256) void gemm_xwx_kernel(
    const float* __restrict__ A, const float* __restrict__ B, int M) {
    __shared__ float As[16][132];
    __shared__ float Bs[16][132];
    int tid = threadIdx.x;
    int m0 = blockIdx.y * 128, n0 = blockIdx.x * 128;
    int tx = tid & 15, ty = tid >> 4;
    int lr = tid >> 2;            // 0..63
    int lc = (tid & 3) << 2;      // 0,4,8,12

    ull acc2[4][8];               // pair over m
    #pragma unroll
    for (int i = 0; i < 4; i++)
        #pragma unroll
        for (int j = 0; j < 8; j++) acc2[i][j] = 0ull;

    const float* Aptr = A + (size_t)(m0 + lr) * Dsz + lc;
    const float* Bptr = B + (size_t)(n0 + lr) * Dsz + lc;

    // preload k0 = 0
    float4 a0 = *(const float4*)(Aptr);
    float4 a1 = *(const float4*)(Aptr + 64 * Dsz);
    float4 b0 = *(const float4*)(Bptr);
    float4 b1 = *(const float4*)(Bptr + 64 * Dsz);

    for (int k0 = 0; k0 < Dsz; k0 += 16) {
        __syncthreads();
        As[lc + 0][lr] = a0.x; As[lc + 1][lr] = a0.y; As[lc + 2][lr] = a0.z; As[lc + 3][lr] = a0.w;
        As[lc + 0][lr + 64] = a1.x; As[lc + 1][lr + 64] = a1.y; As[lc + 2][lr + 64] = a1.z; As[lc + 3][lr + 64] = a1.w;
        Bs[lc + 0][lr] = b0.x; Bs[lc + 1][lr] = b0.y; Bs[lc + 2][lr] = b0.z; Bs[lc + 3][lr] = b0.w;
        Bs[lc + 0][lr + 64] = b1.x; Bs[lc + 1][lr + 64] = b1.y; Bs[lc + 2][lr + 64] = b1.z; Bs[lc + 3][lr + 64] = b1.w;
        __syncthreads();
        if (k0 + 16 < Dsz) {   // prefetch next tile; latency hidden by compute below
            Aptr += 16; Bptr += 16;
            a0 = *(const float4*)(Aptr);
            a1 = *(const float4*)(Aptr + 64 * Dsz);
            b0 = *(const float4*)(Bptr);
            b1 = *(const float4*)(Bptr + 64 * Dsz);
        }
        #pragma unroll
        for (int kk = 0; kk < 16; kk++) {
            ull ap[4];
            ap[0] = *(const ull*)&As[kk][ty * 4 + 0];
            ap[1] = *(const ull*)&As[kk][ty * 4 + 2];
            ap[2] = *(const ull*)&As[kk][64 + ty * 4 + 0];
            ap[3] = *(const ull*)&As[kk][64 + ty * 4 + 2];
            float4 bv0 = *(const float4*)&Bs[kk][tx * 4];
            float4 bv1 = *(const float4*)&Bs[kk][64 + tx * 4];
            ull bd[8];
            bd[0] = f32x2_pack(bv0.x, bv0.x); bd[1] = f32x2_pack(bv0.y, bv0.y);
            bd[2] = f32x2_pack(bv0.z, bv0.z); bd[3] = f32x2_pack(bv0.w, bv0.w);
            bd[4] = f32x2_pack(bv1.x, bv1.x); bd[5] = f32x2_pack(bv1.y, bv1.y);
            bd[6] = f32x2_pack(bv1.z, bv1.z); bd[7] = f32x2_pack(bv1.w, bv1.w);
            #pragma unroll
            for (int i = 0; i < 4; i++)
                #pragma unroll
                for (int j = 0; j < 8; j++)
                    acc2[i][j] = f32x2_fma(ap[i], bd[j], acc2[i][j]);
        }
    }
    #pragma unroll
    for (int i2 = 0; i2 < 4; i2++) {
        float lo[8], hi[8];
        #pragma unroll
        for (int j = 0; j < 8; j++) f32x2_unpack(acc2[i2][j], lo[j], hi[j]);
        #pragma unroll
        for (int r = 0; r < 2; r++) {
            int i = i2 * 2 + r;
            const float* row = r ? hi : lo;
            int m = m0 + ((i < 4) ? (ty * 4 + i) : (64 + ty * 4 + (i - 4)));
            float4 v0 = make_float4(row[0], row[1], row[2], row[3]);
            float4 v1 = make_float4(row[4], row[5], row[6], row[7]);
            *(float4*)&g_Wx[(size_t)m * Dsz + n0 + tx * 4]      = v0;
            *(float4*)&g_Wx[(size_t)m * Dsz + n0 + 64 + tx * 4] = v1;
        }
    }
}

// ---------------- persistent recurrence kernel: 2 interleaved chains/CTA ----------------
// 128 CTAs x 512 threads. CTA c: d-group id = c>>2 (32 d-rows), pair p = c&3.
// It serves TWO independent 4-batch chains (b-groups 2p and 2p+1) with the SAME
// W registers, alternating each round so one chain's compute hides the other's
// sync/staging latency. Warp w owns k-range [64w,64w+64); lane l owns d-row l
// (broadcast LDS). Per-chain per-CTA epoch flags; warp 0 vector-polls the 32
// producer CTAs of the pair.
__global__ __launch_bounds__(RTHREADS, 1) void recur_kernel(
    const float* __restrict__ Wh, const float* __restrict__ bvec,
    const float* __restrict__ bgate, float* __restrict__ outp,
    float* __restrict__ hglob, int T) {
    __shared__ float sh_h[4 * 1024];     // h slice [4 b][1024 k], 16 KB (reused per chain)
    __shared__ float red[16 * 4 * 32];   // [w][b][d-lane] partials, 8 KB
    const int tid = threadIdx.x;
    const int warp = tid >> 5, lane = tid & 31;
    const int p  = blockIdx.x & 3;        // pair index (chains 2p, 2p+1)
    const int id = blockIdx.x >> 2;       // d group (32)
    const int k0 = warp * 64;

    // flags: g_flag[(s*128 + cta)*32] for chain slot s
    unsigned int* my_flag0 = &g_flag[(0 * 128 + blockIdx.x) * 32];
    unsigned int* my_flag1 = &g_flag[(1 * 128 + blockIdx.x) * 32];
    const unsigned int* watch0 = &g_flag[(0 * 128 + 4 * lane + p) * 32];
    const unsigned int* watch1 = &g_flag[(1 * 128 + 4 * lane + p) * 32];

    // weights: lane owns d-row (id*32 + lane), k in [k0, k0+64), packed pairs
    float scale = g_scale;
    ull wp[32];
    {
        const float* wrow = Wh + (size_t)(id * 32 + lane) * Dsz + k0;
        #pragma unroll
        for (int kp = 0; kp < 32; kp++)
            wp[kp] = f32x2_pack(wrow[2 * kp] * scale, wrow[2 * kp + 1] * scale);
    }

    // epilogue role: threads 0..127 own one (b-in-4, d) output of the active chain
    int bo = tid >> 5, dl = tid & 31;            // valid when tid < 128
    int b_base0 = 8 * p, b_base1 = 8 * p + 4;    // chain slot 0 / 1 batch bases
    size_t off0 = (size_t)(b_base0 + bo) * Dsz + (id * 32 + dl);
    size_t off1 = (size_t)(b_base1 + bo) * Dsz + (id * 32 + dl);
    float bias_b = 0.0f, bias_g = 0.0f;
    if (tid < 128) {
        bias_b = bvec[id * 32 + dl];
        bias_g = bgate[id * 32 + dl];
    }

    for (int t = 0; t < T; t++) {
        #pragma unroll
        for (int s = 0; s < 2; s++) {
            const int b_base = s ? b_base1 : b_base0;
            const size_t off = s ? off1 : off0;
            const unsigned int* watch = s ? watch1 : watch0;
            unsigned int* my_flag = s ? my_flag1 : my_flag0;

            // prefetch Wx before any waiting
            float wx = 0.0f;
            if (tid < 128) wx = __ldg(&g_Wx[(size_t)t * BD + off]);

            // wait: warp 0 polls the 32 producer CTAs of this pair (lane i -> CTA 4i+p)
            if (t > 0) {
                if (warp == 0) {
                    unsigned int need = (unsigned int)t;
                    while (!__all_sync(0xffffffffu, ld_acquire_gpu(watch) >= need)) { }
                }
            }
            __syncthreads();   // broadcast readiness + protect sh_h reuse

            // stage h[t] slice: 4 b-rows x 1024 k = 16 KB (2 x LDG.128 / thread)
            {
                const float4* hsrc = (const float4*)(hglob + (size_t)t * BD + (size_t)b_base * Dsz);
                float4* sh4 = (float4*)sh_h;
                #pragma unroll
                for (int i2 = 0; i2 < 2; i2++) {
                    int f = tid + RTHREADS * i2;
                    sh4[f] = __ldcg(&hsrc[f]);
                }
            }
            __syncthreads();

            // partial dot products over this warp's 64-k range, packed pairs
            ull acc2[4];
            #pragma unroll
            for (int b = 0; b < 4; b++) acc2[b] = 0ull;
            #pragma unroll
            for (int j = 0; j < 16; j++) {
                ull w0 = wp[2 * j], w1 = wp[2 * j + 1];
                #pragma unroll
                for (int b = 0; b < 4; b++) {
                    ulonglong2 hv = *(const ulonglong2*)&sh_h[b * 1024 + k0 + j * 4];
                    acc2[b] = f32x2_fma(w0, hv.x, acc2[b]);
                    acc2[b] = f32x2_fma(w1, hv.y, acc2[b]);
                }
            }
            // write k-partials: red[warp][b][lane]
            #pragma unroll
            for (int b = 0; b < 4; b++) {
                float lo, hi;
                f32x2_unpack(acc2[b], lo, hi);
                red[warp * 128 + b * 32 + lane] = lo + hi;
            }
            __syncthreads();

            // reduce 16 warp-partials; store h_new first (critical path)
            float h_new = 0.0f;
            if (tid < 128) {
                float sum = 0.0f;
                #pragma unroll
                for (int w = 0; w < 16; w++) sum += red[w * 128 + tid];
                float raw = sum + wx + bias_b;
                h_new = tanhf(raw);
                hglob[(size_t)(t + 1) * BD + off] = h_new;
            }

            // publish h_new: cta barrier (orders all STGs) + release to own chain flag
            __syncthreads();
            if (tid == 0) red_release_gpu_add(my_flag, 1u);

            // off-critical-path epilogue: gate + output store
            if (tid < 128) {
                float g = wx + h_new + bias_g;
                float outv = h_new * (g / (1.0f + __expf(-g)));
                outp[(size_t)t * BD + off] = outv;
            }
        }
    }
}

// ---------------- launch ----------------
extern "C" void kernel_launch(void* const* d_in, const int* in_sizes, int n_in,
                              void* d_out, int out_size) {
    const float* x   = (const float*)d_in[0];
    // d_in[1] = z (unused by reference in this gate mode)
    const float* h0  = (const float*)d_in[2];
    const float* W_x = (const float*)d_in[3];
    const float* W_h = (const float*)d_in[4];
    const float* bv  = (const float*)d_in[5];
    const float* bg  = (const float*)d_in[6];
    const float* u0  = (const float*)d_in[7];

    int T = in_sizes[0] / BD;
    float* outp  = (float*)d_out;                 // [T, B, D]
    float* hglob = outp + (size_t)T * BD;         // [T+1, B, D]

    reset_copy_kernel<<<32, 1024>>>(h0, hglob);
    spectral_kernel<<<1, 1024>>>(W_h, u0);
    dim3 grid_g(Dsz / 128, (T * Bsz) / 128);
    gemm_xwx_kernel<<<grid_g, 256>>>(x, W_x, T * Bsz);
    recur_kernel<<<NBLK, RTHREADS>>>(W_h, bv, bg, outp, hglob, T);
}

// round 12
// speedup vs baseline: 1.2772x; 1.2772x over previous
#include <cuda_runtime.h>
#include <math.h>
#include <cstdint>

#define EPS 1e-8f
#define TARGET_RADIUS 0.99f
#define Bsz 32
#define Dsz 1024
#define BD (Bsz * Dsz)
#define NBLK 128   // recurrence grid size (single wave)
#define RTHREADS 512

typedef unsigned long long ull;

// ---------------- packed f32x2 helpers (sm_103a) ----------------
__device__ __forceinline__ ull f32x2_pack(float lo, float hi) {
    ull r;
    asm("mov.b64 %0, {%1, %2};" : "=l"(r) : "f"(lo), "f"(hi));
    return r;
}
__device__ __forceinline__ void f32x2_unpack(ull p, float& lo, float& hi) {
    asm("mov.b64 {%0, %1}, %2;" : "=f"(lo), "=f"(hi) : "l"(p));
}
__device__ __forceinline__ ull f32x2_fma(ull a, ull b, ull c) {
    ull d;
    asm("fma.rn.f32x2 %0, %1, %2, %3;" : "=l"(d) : "l"(a), "l"(b), "l"(c));
    return d;
}

// ---------------- device scratch ----------------
__device__ float g_Wx[2048L * Bsz * Dsz];     // x @ W_x^T, produced concurrently (268 MB)
__device__ float g_scale;                     // spectral scaling of W_h
__device__ unsigned int g_flag[128 * 32];     // per-CTA recurrence step flags, 128B padded
__device__ unsigned int g_wx_ready[1024];     // per-64-row-chunk Wx readiness (16 tiles each)

// ---------------- scoped atomic helpers ----------------
__device__ __forceinline__ unsigned int ld_acquire_gpu(const unsigned int* p) {
    unsigned int v;
    asm volatile("ld.acquire.gpu.global.u32 %0, [%1];" : "=r"(v) : "l"(p) : "memory");
    return v;
}
__device__ __forceinline__ void red_release_gpu_add(unsigned int* p, unsigned int v) {
    asm volatile("red.release.gpu.global.add.u32 [%0], %1;" :: "l"(p), "r"(v) : "memory");
}

// ---------------- reset + h0 copy ----------------
__global__ void reset_copy_kernel(const float* __restrict__ h0, float* __restrict__ hglob) {
    int i = blockIdx.x * blockDim.x + threadIdx.x;
    if (i < 128 * 32) g_flag[i] = 0u;
    if (i < 1024) g_wx_ready[i] = 0u;
    if (i < BD) hglob[i] = h0[i];
}

// ---------------- block reduction helper ----------------
__device__ __forceinline__ float block_reduce_sum(float v, float* red) {
    int lane = threadIdx.x & 31, w = threadIdx.x >> 5;
    #pragma unroll
    for (int o = 16; o; o >>= 1) v += __shfl_xor_sync(0xffffffffu, v, o);
    if (lane == 0) red[w] = v;
    __syncthreads();
    if (w == 0) {
        float r = (lane < (int)(blockDim.x >> 5)) ? red[lane] : 0.0f;
        #pragma unroll
        for (int o = 16; o; o >>= 1) r += __shfl_xor_sync(0xffffffffu, r, o);
        if (lane == 0) red[0] = r;
    }
    __syncthreads();
    float out = red[0];
    __syncthreads();
    return out;
}

// ---------------- spectral norm (1 CTA, 1024 threads) ----------------
__global__ __launch_bounds__(1024) void spectral_kernel(
    const float* __restrict__ W, const float* __restrict__ u0) {
    __shared__ float u_sh[Dsz];
    __shared__ float v_sh[Dsz];
    __shared__ float ur[Dsz];
    __shared__ float red[32];
    int i = threadIdx.x;
    int warp = i >> 5, lane = i & 31;

    float u0v = u0[i];
    float n0 = sqrtf(block_reduce_sum(u0v * u0v, red));
    u_sh[i] = u0v / n0;
    __syncthreads();

    float sigma = 0.0f;
    for (int it = 0; it < 3; it++) {
        // v = W^T u (thread i = column i, coalesced)
        float acc = 0.0f;
        #pragma unroll 8
        for (int k = 0; k < Dsz; k++) acc += W[k * Dsz + i] * u_sh[k];
        float nv = sqrtf(block_reduce_sum(acc * acc, red));
        v_sh[i] = acc / (nv + EPS);
        __syncthreads();
        // u_raw = W v: warp per 32 rows, lanes coalesced within each row
        const float4* v4 = (const float4*)v_sh;
        for (int rl = 0; rl < 32; rl++) {
            int row = warp * 32 + rl;
            const float4* Wr = (const float4*)(W + (size_t)row * Dsz);
            float a = 0.0f;
            #pragma unroll
            for (int j = 0; j < 8; j++) {
                float4 wv = Wr[j * 32 + lane];
                float4 vv = v4[j * 32 + lane];
                a += wv.x * vv.x + wv.y * vv.y + wv.z * vv.z + wv.w * vv.w;
            }
            #pragma unroll
            for (int o = 16; o; o >>= 1) a += __shfl_xor_sync(0xffffffffu, a, o);
            if (lane == 0) ur[row] = a;
        }
        __syncthreads();
        float acc2 = ur[i];
        float ss = block_reduce_sum(acc2 * acc2, red);
        float nu = sqrtf(ss);
        u_sh[i] = acc2 / (nu + EPS);
        __syncthreads();
        sigma = ss / (nu + EPS);
    }
    if (i == 0) g_scale = TARGET_RADIUS / (sigma + EPS);
}

// ---------------- co-resident Wx GEMM: 64x64 tiles, 128 threads, <=88 regs ----------------
// C[64mt.., 64nt..] = A[64 rows,1024] @ B[64 rows,1024]^T. Tiles complete mt-major;
// each tile releases g_wx_ready[mt] (chunk ready at 16). Runs CONCURRENTLY with the
// recurrence in its spare issue slots (co-residency guaranteed by register budget:
// 512*104 + 128*88 = 64512 <= 65536 regs/SM).
__global__ void __maxnreg__(88) gemm64_kernel(
    const float* __restrict__ A, const float* __restrict__ B) {
    __shared__ float As[16][68];
    __shared__ float Bs[16][68];
    int tid = threadIdx.x;
    int m0 = blockIdx.y * 64, n0 = blockIdx.x * 64;
    int tx = tid & 15, ty = tid >> 4;     // tx: n/4 (16), ty: m/4 per half (8)
    int lr = tid >> 1;                    // 0..63
    int lc = (tid & 1) * 8;               // 0 or 8

    ull acc2[4][4];                       // (m-pair [4] over 8 rows) x (n [4])
    #pragma unroll
    for (int i = 0; i < 4; i++)
        #pragma unroll
        for (int j = 0; j < 4; j++) acc2[i][j] = 0ull;

    const float* Aptr = A + (size_t)(m0 + lr) * Dsz + lc;
    const float* Bptr = B + (size_t)(n0 + lr) * Dsz + lc;

    float4 a0 = *(const float4*)(Aptr);
    float4 a1 = *(const float4*)(Aptr + 4);
    float4 b0 = *(const float4*)(Bptr);
    float4 b1 = *(const float4*)(Bptr + 4);

    for (int k0 = 0; k0 < Dsz; k0 += 16) {
        __syncthreads();
        As[lc + 0][lr] = a0.x; As[lc + 1][lr] = a0.y; As[lc + 2][lr] = a0.z; As[lc + 3][lr] = a0.w;
        As[lc + 4][lr] = a1.x; As[lc + 5][lr] = a1.y; As[lc + 6][lr] = a1.z; As[lc + 7][lr] = a1.w;
        Bs[lc + 0][lr] = b0.x; Bs[lc + 1][lr] = b0.y; Bs[lc + 2][lr] = b0.z; Bs[lc + 3][lr] = b0.w;
        Bs[lc + 4][lr] = b1.x; Bs[lc + 5][lr] = b1.y; Bs[lc + 6][lr] = b1.z; Bs[lc + 7][lr] = b1.w;
        __syncthreads();
        if (k0 + 16 < Dsz) {
            Aptr += 16; Bptr += 16;
            a0 = *(const float4*)(Aptr);
            a1 = *(const float4*)(Aptr + 4);
            b0 = *(const float4*)(Bptr);
            b1 = *(const float4*)(Bptr + 4);
        }
        #pragma unroll
        for (int kk = 0; kk < 16; kk++) {
            ull ap[4];
            ap[0] = *(const ull*)&As[kk][ty * 4 + 0];
            ap[1] = *(const ull*)&As[kk][ty * 4 + 2];
            ap[2] = *(const ull*)&As[kk][32 + ty * 4 + 0];
            ap[3] = *(const ull*)&As[kk][32 + ty * 4 + 2];
            float4 bv = *(const float4*)&Bs[kk][tx * 4];
            ull bd[4];
            bd[0] = f32x2_pack(bv.x, bv.x); bd[1] = f32x2_pack(bv.y, bv.y);
            bd[2] = f32x2_pack(bv.z, bv.z); bd[3] = f32x2_pack(bv.w, bv.w);
            #pragma unroll
            for (int i = 0; i < 4; i++)
                #pragma unroll
                for (int j = 0; j < 4; j++)
                    acc2[i][j] = f32x2_fma(ap[i], bd[j], acc2[i][j]);
        }
    }
    // epilogue: 8 m-rows x 4 n-cols per thread
    #pragma unroll
    for (int i2 = 0; i2 < 4; i2++) {
        float lo[4], hi[4];
        #pragma unroll
        for (int j = 0; j < 4; j++) f32x2_unpack(acc2[i2][j], lo[j], hi[j]);
        int mbase = m0 + ((i2 < 2) ? (ty * 4 + i2 * 2) : (32 + ty * 4 + (i2 - 2) * 2));
        *(float4*)&g_Wx[(size_t)mbase * Dsz + n0 + tx * 4] =
            make_float4(lo[0], lo[1], lo[2], lo[3]);
        *(float4*)&g_Wx[(size_t)(mbase + 1) * Dsz + n0 + tx * 4] =
            make_float4(hi[0], hi[1], hi[2], hi[3]);
    }
    // publish tile: cta barrier orders all threads' stores, then one release-red
    __syncthreads();
    if (tid == 0) red_release_gpu_add(&g_wx_ready[blockIdx.y], 1u);
}

// ---------------- persistent recurrence kernel (R8 structure + Wx readiness) ----------------
__global__ void __maxnreg__(104) recur_kernel(
    const float* __restrict__ Wh, const float* __restrict__ bvec,
    const float* __restrict__ bgate, float* __restrict__ outp,
    float* __restrict__ hglob, int T) {
    __shared__ float sh_h[8 * 1024];     // h slice [b][k], 32 KB
    __shared__ float red[16 * 8 * 32];   // [w][b][d-lane] partials, 16 KB
    const int tid = threadIdx.x;
    const int warp = tid >> 5, lane = tid & 31;
    const int ib = blockIdx.x & 3;
    const int id = blockIdx.x >> 2;
    const int b_base = ib * 8;
    const int k0 = warp * 64;

    unsigned int* my_flag = &g_flag[blockIdx.x * 32];
    const unsigned int* watch_flag = &g_flag[(lane * 4 + ib) * 32];

    float scale = g_scale;
    ull wp[32];
    {
        const float* wrow = Wh + (size_t)(id * 32 + lane) * Dsz + k0;
        #pragma unroll
        for (int kp = 0; kp < 32; kp++)
            wp[kp] = f32x2_pack(wrow[2 * kp] * scale, wrow[2 * kp + 1] * scale);
    }

    int bo = tid >> 5, dl = tid & 31;
    size_t off = (size_t)(b_base + bo) * Dsz + (id * 32 + dl);
    float bias_b = 0.0f, bias_g = 0.0f;
    if (tid < 256) {
        bias_b = bvec[id * 32 + dl];
        bias_g = bgate[id * 32 + dl];
    }

    for (int t = 0; t < T; t++) {
        // wait: warp 0 polls Wx-chunk readiness (concurrent GEMM) + 32 producer CTAs
        if (warp == 0) {
            const unsigned int* rdy = &g_wx_ready[t >> 1];
            while (ld_acquire_gpu(rdy) < 16u) { }
            if (t > 0) {
                unsigned int need = (unsigned int)t;
                while (!__all_sync(0xffffffffu, ld_acquire_gpu(watch_flag) >= need)) { }
            }
        }
        __syncthreads();

        // wx load (safe now; latency overlaps staging LDGs below)
        float wx = 0.0f;
        if (tid < 256) wx = __ldcg(&g_Wx[(size_t)t * BD + off]);

        // stage h[t] slice (compute reads are warp-uniform broadcasts)
        {
            const float4* hsrc = (const float4*)(hglob + (size_t)t * BD + (size_t)b_base * Dsz);
            float4* sh4 = (float4*)sh_h;
            #pragma unroll
            for (int i2 = 0; i2 < 4; i2++) {
                int f = tid + RTHREADS * i2;
                sh4[f] = __ldcg(&hsrc[f]);
            }
        }
        __syncthreads();

        ull acc2[8];
        #pragma unroll
        for (int b = 0; b < 8; b++) acc2[b] = 0ull;
        #pragma unroll
        for (int j = 0; j < 16; j++) {
            ull w0 = wp[2 * j], w1 = wp[2 * j + 1];
            #pragma unroll
            for (int b = 0; b < 8; b++) {
                ulonglong2 hv = *(const ulonglong2*)&sh_h[b * 1024 + k0 + j * 4];
                acc2[b] = f32x2_fma(w0, hv.x, acc2[b]);
                acc2[b] = f32x2_fma(w1, hv.y, acc2[b]);
            }
        }
        #pragma unroll
        for (int b = 0; b < 8; b++) {
            float lo, hi;
            f32x2_unpack(acc2[b], lo, hi);
            red[warp * 256 + b * 32 + lane] = lo + hi;
        }
        __syncthreads();

        float h_new = 0.0f;
        if (tid < 256) {
            float s = 0.0f;
            #pragma unroll
            for (int w = 0; w < 16; w++) s += red[w * 256 + tid];
            float raw = s + wx + bias_b;
            h_new = tanhf(raw);
            hglob[(size_t)(t + 1) * BD + off] = h_new;
        }

        __syncthreads();
        if (tid == 0) red_release_gpu_add(my_flag, 1u);

        // off-critical-path epilogue
        if (tid < 256) {
            float g = wx + h_new + bias_g;
            float outv = h_new * (g / (1.0f + __expf(-g)));
            outp[(size_t)t * BD + off] = outv;
        }
    }
}

// ---------------- launch: fork GEMM onto a side stream, concurrent with recurrence ----------------
extern "C" void kernel_launch(void* const* d_in, const int* in_sizes, int n_in,
                              void* d_out, int out_size) {
    const float* x   = (const float*)d_in[0];
    const float* h0  = (const float*)d_in[2];
    const float* W_x = (const float*)d_in[3];
    const float* W_h = (const float*)d_in[4];
    const float* bv  = (const float*)d_in[5];
    const float* bg  = (const float*)d_in[6];
    const float* u0  = (const float*)d_in[7];

    int T = in_sizes[0] / BD;
    float* outp  = (float*)d_out;                 // [T, B, D]
    float* hglob = outp + (size_t)T * BD;         // [T+1, B, D]

    // lazy-create side stream + events on the (uncaptured) correctness run
    static cudaStream_t s2 = nullptr;
    static cudaEvent_t evFork = nullptr, evJoin = nullptr;
    if (s2 == nullptr) {
        cudaStreamCreateWithFlags(&s2, cudaStreamNonBlocking);
        cudaEventCreateWithFlags(&evFork, cudaEventDisableTiming);
        cudaEventCreateWithFlags(&evJoin, cudaEventDisableTiming);
    }

    // prologue (zeroes flags/readiness; copies h0; computes spectral scale)
    reset_copy_kernel<<<32, 1024>>>(h0, hglob);
    spectral_kernel<<<1, 1024>>>(W_h, u0);

    // fork: GEMM on side stream, recurrence on main stream — concurrent
    cudaEventRecord(evFork, 0);
    cudaStreamWaitEvent(s2, evFork, 0);

    dim3 grid_g(Dsz / 64, (T * Bsz) / 64);        // (16 n-tiles, mt chunks) — mt-major completion
    gemm64_kernel<<<grid_g, 128, 0, s2>>>(x, W_x);

    recur_kernel<<<NBLK, RTHREADS>>>(W_h, bv, bg, outp, hglob, T);

    // join: main stream waits for GEMM completion
    cudaEventRecord(evJoin, s2);
    cudaStreamWaitEvent(0, evJoin, 0);
}